// round 12
// baseline (speedup 1.0000x reference)
#include <cuda_runtime.h>
#include <math.h>

// Problem constants (fixed by this dataset instance)
constexpr int B = 16, P = 19248, C = 81, G = 16;
constexpr float VAR0 = 0.1f, VAR1 = 0.2f;
constexpr float POS_T = 0.5f, NEG_T = 0.4f;
constexpr int   NPR = 3;
constexpr float BBOX_ALPHA = 1.5f, CONF_ALPHA = 1.0f;

constexpr int TILE = 48;            // priors per k_conf block (48*401 == P exactly)
constexpr int CONF_THREADS = 384;   // 8 threads per prior row
constexpr int NB1 = 2048;           // bits >> 20   (bit31 == 0 since lc >= 0)

// -------- scratch (device globals; no allocation allowed) --------
__device__ unsigned long long g_bestgt[B * G];
__device__ float              g_sl1   [B * P];
__device__ unsigned           g_lcbits[B * P];
__device__ float              g_ce    [B * P];
__device__ unsigned char      g_state [B * P];   // 0=neg, 1=pos, 2=neutral
__device__ int                g_numpos[B];
__device__ double             g_acc   [2];
__device__ unsigned           g_done;

// -------- kernel 0: reset (single tiny block) --------
__global__ void k_reset() {
    int t = threadIdx.x;
    if (t < B * G) g_bestgt[t] = 0ULL;
    if (t < B)     g_numpos[t] = 0;
    if (t < 2)     g_acc[t] = 0.0;
    if (t == 0)    g_done = 0u;
}

// -------- kernel 1: per-GT best prior only --------
__global__ void k_match(const float4* __restrict__ priors4,
                        const float* __restrict__ gtb) {
    __shared__ float sg[G * 4];
    __shared__ float sga[G];
    __shared__ unsigned long long sbest[G];
    int b = blockIdx.y;
    int t = threadIdx.x;
    if (t < G * 4) sg[t] = gtb[b * G * 4 + t];
    if (t < G)     sbest[t] = 0ULL;
    __syncthreads();
    if (t < G)     sga[t] = (sg[t*4+2] - sg[t*4+0]) * (sg[t*4+3] - sg[t*4+1]);
    __syncthreads();

    int p = blockIdx.x * blockDim.x + t;
    if (p < P) {
        float4 pr = priors4[(size_t)b * P + p];
        float bx1 = pr.x - 0.5f * pr.z, by1 = pr.y - 0.5f * pr.w;
        float bx2 = pr.x + 0.5f * pr.z, by2 = pr.y + 0.5f * pr.w;
        float areaB = pr.z * pr.w;
        #pragma unroll
        for (int g = 0; g < G; g++) {
            float iw = fmaxf(fminf(sg[g*4+2], bx2) - fmaxf(sg[g*4+0], bx1), 0.0f);
            float ih = fmaxf(fminf(sg[g*4+3], by2) - fmaxf(sg[g*4+1], by1), 0.0f);
            float inter = iw * ih;
            float iou = inter / fmaxf(sga[g] + areaB - inter, 1e-10f);
            unsigned long long key =
                ((unsigned long long)__float_as_uint(iou) << 32) |
                (unsigned long long)(0xFFFFFFFFu - (unsigned)p);  // max iou, then min p
            atomicMax(&sbest[g], key);
        }
    }
    __syncthreads();
    if (t < G) atomicMax(&g_bestgt[b * G + t], sbest[t]);
}

// -------- kernel 2: conf loss pieces + match recompute + force-match + SL1 --------
__global__ __launch_bounds__(CONF_THREADS)
void k_conf(const float* __restrict__ conf,
            const float* __restrict__ loc,
            const float* __restrict__ priors,
            const float* __restrict__ gtb,
            const int*   __restrict__ gtl) {
    __shared__ float sconf[TILE * C];          // 15552 B
    __shared__ int   sbestp[G];
    __shared__ int   slab[G];
    __shared__ float sgb[G * 4];
    __shared__ float sga[G];
    __shared__ int   s_pos[CONF_THREADS / 32];

    int b    = blockIdx.y;
    int tile = blockIdx.x;
    int t    = threadIdx.x;

    if (t < G) {
        unsigned long long key = g_bestgt[b * G + t];
        sbestp[t] = (int)(0xFFFFFFFFu - (unsigned)(key & 0xFFFFFFFFull));
        slab[t]   = gtl[b * G + t];
    }
    if (t < G * 4) sgb[t] = gtb[b * G * 4 + t];

    {
        const float4* src = (const float4*)(conf + ((size_t)b * P + (size_t)tile * TILE) * C);
        float4* dst = (float4*)sconf;
        constexpr int N4 = TILE * C / 4;   // 972
        for (int i = t; i < N4; i += CONF_THREADS) dst[i] = src[i];
    }
    __syncthreads();
    if (t < G) sga[t] = (sgb[t*4+2] - sgb[t*4+0]) * (sgb[t*4+3] - sgb[t*4+1]);
    __syncthreads();

    int row = t >> 3;           // 0..47
    int sub = t & 7;            // 0..7
    const float* srow = sconf + row * C;

    float v[11];
    #pragma unroll
    for (int i = 0; i < 11; i++) {
        int j = sub + i * 8;
        v[i] = (j < C) ? srow[j] : -1e30f;
    }
    float m = v[0];
    #pragma unroll
    for (int i = 1; i < 11; i++) m = fmaxf(m, v[i]);
    m = fmaxf(m, __shfl_xor_sync(0xffffffffu, m, 1));
    m = fmaxf(m, __shfl_xor_sync(0xffffffffu, m, 2));
    m = fmaxf(m, __shfl_xor_sync(0xffffffffu, m, 4));
    float s = 0.0f;
    #pragma unroll
    for (int i = 0; i < 11; i++) s += __expf(v[i] - m);
    s += __shfl_xor_sync(0xffffffffu, s, 1);
    s += __shfl_xor_sync(0xffffffffu, s, 2);
    s += __shfl_xor_sync(0xffffffffu, s, 4);

    bool is_pos = false;
    if (sub == 0) {
        float lse = m + logf(s);
        int p   = tile * TILE + row;
        int idx = b * P + p;
        // recompute per-prior match (bit-identical to k_match arithmetic)
        const float4 pr = *(const float4*)(priors + (size_t)idx * 4);
        float bx1 = pr.x - 0.5f * pr.z, by1 = pr.y - 0.5f * pr.w;
        float bx2 = pr.x + 0.5f * pr.z, by2 = pr.y + 0.5f * pr.w;
        float areaB = pr.z * pr.w;
        float bo = -1.0f; int bi = 0;
        #pragma unroll
        for (int g = 0; g < G; g++) {
            float iw = fmaxf(fminf(sgb[g*4+2], bx2) - fmaxf(sgb[g*4+0], bx1), 0.0f);
            float ih = fmaxf(fminf(sgb[g*4+3], by2) - fmaxf(sgb[g*4+1], by1), 0.0f);
            float inter = iw * ih;
            float iou = inter / fmaxf(sga[g] + areaB - inter, 1e-10f);
            if (iou > bo) { bo = iou; bi = g; }   // first-index argmax
        }
        // force-match (ascending g == sequential scatter, last wins)
        #pragma unroll
        for (int g = 0; g < G; g++)
            if (sbestp[g] == p) { bo = 2.0f; bi = g; }

        int lab = slab[bi];
        int conf_t = (bo < POS_T) ? ((bo < NEG_T) ? 0 : -1) : lab;
        bool pos = conf_t > 0;
        is_pos = pos;
        int tgt = pos ? conf_t : 0;
        float ce = lse - srow[tgt];
        float lc = (pos || conf_t < 0) ? 0.0f : (lse - srow[0]);
        g_ce[idx]     = ce;
        g_lcbits[idx] = __float_as_uint(lc);      // lc >= 0: bits monotonic
        g_state[idx]  = pos ? 1 : (conf_t < 0 ? 2 : 0);
        float sl = 0.0f;
        if (pos) {
            const float4 ld = *(const float4*)(loc + (size_t)idx * 4);
            float gx1 = sgb[bi*4+0], gy1 = sgb[bi*4+1];
            float gx2 = sgb[bi*4+2], gy2 = sgb[bi*4+3];
            float t0 = ((gx1 + gx2) * 0.5f - pr.x) / (VAR0 * pr.z);
            float t1 = ((gy1 + gy2) * 0.5f - pr.y) / (VAR0 * pr.w);
            float t2 = logf(fmaxf((gx2 - gx1) / pr.z, 1e-8f)) / VAR1;
            float t3 = logf(fmaxf((gy2 - gy1) / pr.w, 1e-8f)) / VAR1;
            float d;
            d = ld.x - t0; sl += (fabsf(d) < 1.0f) ? 0.5f * d * d : fabsf(d) - 0.5f;
            d = ld.y - t1; sl += (fabsf(d) < 1.0f) ? 0.5f * d * d : fabsf(d) - 0.5f;
            d = ld.z - t2; sl += (fabsf(d) < 1.0f) ? 0.5f * d * d : fabsf(d) - 0.5f;
            d = ld.w - t3; sl += (fabsf(d) < 1.0f) ? 0.5f * d * d : fabsf(d) - 0.5f;
        }
        g_sl1[idx] = sl;
    }
    unsigned bal = __ballot_sync(0xffffffffu, is_pos);
    if ((t & 31) == 0) s_pos[t >> 5] = __popc(bal);
    __syncthreads();
    if (t == 0) {
        int c = 0;
        #pragma unroll
        for (int w = 0; w < CONF_THREADS / 32; w++) c += s_pos[w];
        if (c) atomicAdd(&g_numpos[b], c);
    }
}

// ---- shuffle-based block suffix sum (1024 threads): returns sum_{j>=t} c_j ----
__device__ __forceinline__ int block_suffix_incl(int c, int t, int* wsmem) {
    int lane = t & 31, w = t >> 5;
    int v = c;
    #pragma unroll
    for (int off = 1; off < 32; off <<= 1) {
        int u = __shfl_down_sync(0xffffffffu, v, off);
        if (lane + off < 32) v += u;
    }
    if (lane == 0) wsmem[w] = v;   // warp total
    __syncthreads();
    if (t < 32) {
        int x = wsmem[t];
        #pragma unroll
        for (int off = 1; off < 32; off <<= 1) {
            int u = __shfl_down_sync(0xffffffffu, x, off);
            if (t + off < 32) x += u;
        }
        wsmem[t] = x;              // suffix of warp totals, incl own warp
    }
    __syncthreads();
    int add = (w + 1 < 32) ? wsmem[w + 1] : 0;
    return v + add;
}

// -------- kernel 3: FUSED selection (3-level radix via smem hist) + final sums + out --------
__global__ __launch_bounds__(1024)
void k_select(float* __restrict__ out) {
    __shared__ unsigned hist[NB1];   // 8KB, reused at each level
    __shared__ int wsmem[32];
    __shared__ int s_hb1, s_r1, s_hb2, s_r2, s_r3, s_cut;
    __shared__ unsigned s_T;
    __shared__ float sB[32], sC[32];

    int b = blockIdx.x, t = threadIdx.x;
    const unsigned* lc = g_lcbits + b * P;
    int numpos = g_numpos[b];
    int k = NPR * numpos;
    if (k > P - 1) k = P - 1;

    // ---- level 1: 2048 bins on bits>>20 ----
    hist[t] = 0u; hist[t + 1024] = 0u;
    __syncthreads();
    for (int p = t; p < P; p += 1024) atomicAdd(&hist[lc[p] >> 20], 1u);
    __syncthreads();
    {
        int c0 = (int)hist[2 * t], c1 = (int)hist[2 * t + 1];
        int S = block_suffix_incl(c0 + c1, t, wsmem);
        int above = S - c0 - c1;
        if (above < k && k <= above + c1) { s_hb1 = 2 * t + 1; s_r1 = k - above; }
        else if (above + c1 < k && k <= above + c1 + c0) { s_hb1 = 2 * t; s_r1 = k - above - c1; }
    }
    __syncthreads();
    int hb1 = s_hb1, r1 = s_r1;

    // ---- level 2: 1024 bins on (bits>>10)&0x3FF, predicated ----
    hist[t] = 0u;
    __syncthreads();
    for (int p = t; p < P; p += 1024) {
        unsigned v = lc[p];
        if ((int)(v >> 20) == hb1) atomicAdd(&hist[(v >> 10) & 0x3FFu], 1u);
    }
    __syncthreads();
    {
        int c = (int)hist[t];
        int S = block_suffix_incl(c, t, wsmem);
        int above = S - c;
        if (above < r1 && r1 <= above + c) { s_hb2 = t; s_r2 = r1 - above; }
    }
    __syncthreads();
    int hb2 = s_hb2, r2 = s_r2;
    unsigned pref = ((unsigned)hb1 << 10) | (unsigned)hb2;

    // ---- level 3: 1024 bins on bits&0x3FF, predicated ----
    hist[t] = 0u;
    __syncthreads();
    for (int p = t; p < P; p += 1024) {
        unsigned v = lc[p];
        if ((v >> 10) == pref) atomicAdd(&hist[v & 0x3FFu], 1u);
    }
    __syncthreads();
    {
        int c = (int)hist[t];
        int S = block_suffix_incl(c, t, wsmem);
        int above = S - c;
        if (above < r2 && r2 <= above + c) {
            s_T  = (pref << 10) | (unsigned)t;
            s_r3 = r2 - above;
        }
    }
    __syncthreads();
    unsigned T = s_T;
    int r3 = s_r3;

    // ---- tie cutoff: r3-th occurrence of bits==T in index order ----
    {
        constexpr int CHUNK = (P + 1023) / 1024;   // 19
        int beg = t * CHUNK;
        int end = min(beg + CHUNK, P);
        int cnt = 0;
        for (int p = beg; p < end; p++) cnt += (lc[p] == T);
        // inclusive prefix sum over chunk counts
        int lane = t & 31, w = t >> 5;
        int v = cnt;
        #pragma unroll
        for (int off = 1; off < 32; off <<= 1) {
            int u = __shfl_up_sync(0xffffffffu, v, off);
            if (lane >= off) v += u;
        }
        if (lane == 31) wsmem[w] = v;
        __syncthreads();
        if (t < 32) {
            int x = wsmem[t];
            #pragma unroll
            for (int off = 1; off < 32; off <<= 1) {
                int u = __shfl_up_sync(0xffffffffu, x, off);
                if (t >= off) x += u;
            }
            wsmem[t] = x;
        }
        __syncthreads();
        int excl = ((w > 0) ? wsmem[w - 1] : 0) + v - cnt;
        if (excl < r3 && r3 <= excl + cnt) {
            int want = r3 - excl;
            for (int p = beg; p < end; p++) {
                if (lc[p] == T && --want == 0) { s_cut = p; break; }
            }
        }
    }
    __syncthreads();
    int cut = s_cut;

    // ---- final masked sums for this image ----
    float invnp = 1.0f / (float)max(numpos, 1);
    float cB = 0.0f, cC = 0.0f;
    for (int p = t; p < P; p += 1024) {
        int idx = b * P + p;
        int st = g_state[idx];
        unsigned bits = lc[p];
        bool neg = (st == 0) && (bits > T || (bits == T && p <= cut));
        bool pos = (st == 1);
        if (pos) cB += g_sl1[idx] * invnp;
        if (pos || neg) cC += g_ce[idx];
    }
    #pragma unroll
    for (int o = 16; o > 0; o >>= 1) {
        cB += __shfl_xor_sync(0xffffffffu, cB, o);
        cC += __shfl_xor_sync(0xffffffffu, cC, o);
    }
    int w = t >> 5;
    if ((t & 31) == 0) { sB[w] = cB; sC[w] = cC; }
    __syncthreads();
    if (t == 0) {
        float tB = 0.0f, tC = 0.0f;
        #pragma unroll
        for (int i = 0; i < 32; i++) { tB += sB[i]; tC += sC[i]; }
        atomicAdd(&g_acc[0], (double)tB);
        atomicAdd(&g_acc[1], (double)tC);
        __threadfence();
        unsigned old = atomicAdd(&g_done, 1u);
        if (old == B - 1) {
            out[0] = (float)(g_acc[0] * (double)BBOX_ALPHA / (double)B);
            out[1] = (float)(g_acc[1] * (double)CONF_ALPHA / (double)B);
        }
    }
}

extern "C" void kernel_launch(void* const* d_in, const int* in_sizes, int n_in,
                              void* d_out, int out_size) {
    const float* loc    = (const float*)d_in[0];
    const float* conf   = (const float*)d_in[1];
    const float* priors = (const float*)d_in[2];
    const float* gtb    = (const float*)d_in[3];
    const int*   gtl    = (const int*)d_in[4];
    float* out = (float*)d_out;

    k_reset<<<1, 256>>>();
    {
        dim3 grid((P + 255) / 256, B);
        k_match<<<grid, 256>>>((const float4*)priors, gtb);
    }
    {
        dim3 grid(P / TILE, B);   // 401 x 16
        k_conf<<<grid, CONF_THREADS>>>(conf, loc, priors, gtb, gtl);
    }
    k_select<<<B, 1024>>>(out);
}